// round 5
// baseline (speedup 1.0000x reference)
#include <cuda_runtime.h>
#include <cstdint>

#define B_TOTAL   8192
#define LEAK      0.01f
#define BN_EPS    1e-5f

// -------------------- global scratch --------------------
__device__ float g_conv[64 * 90 * B_TOTAL];   // conv1 out [64][10][9][B]
__device__ float g_y1[16 * 50 * B_TOTAL];
__device__ float g_y2[8 * 66 * B_TOTAL];
__device__ float g_y3[8 * 48 * B_TOTAL];
__device__ float g_part1[800 * 32];
__device__ float g_part2[1056 * 16];
__device__ float g_part3[768 * 16];
__device__ float g_bnA1[16], g_bnB1[16];
__device__ float g_bnA2[8],  g_bnB2[8];
__device__ float g_bnA3[8],  g_bnB3[8];

typedef unsigned long long u64;

__device__ __forceinline__ float lrelu(float v) { return v < 0.f ? LEAK * v : v; }
__device__ __forceinline__ float wsum(float v) {
#pragma unroll
    for (int s = 16; s; s >>= 1) v += __shfl_xor_sync(0xffffffffu, v, s);
    return v;
}
__device__ __forceinline__ u64 dup2f(float v) {
    u64 r; asm("mov.b64 %0, {%1, %1};" : "=l"(r) : "f"(v)); return r;
}
#define FMA2(d, a, b)   asm("fma.rn.f32x2 %0, %1, %2, %0;" : "+l"(d) : "l"(a), "l"(b))
#define UNPK(lo, hi, v) asm("mov.b64 {%0, %1}, %2;" : "=f"(lo), "=f"(hi) : "l"(v))

#define CH8(ar, s)                                              \
    FMA2(ar[0], s, wA.x); FMA2(ar[1], s, wA.y);                 \
    FMA2(ar[2], s, wB.x); FMA2(ar[3], s, wB.y);                 \
    FMA2(ar[4], s, wC.x); FMA2(ar[5], s, wC.y);                 \
    FMA2(ar[6], s, wD.x); FMA2(ar[7], s, wD.y);

// ============================ K0: conv1 + lrelu ===============================
#define SMEM0 ((256 * 91 + 32 + 8) * 4)
__global__ void k0_conv1(const float* __restrict__ img,
                         const float* __restrict__ w1,
                         const float* __restrict__ b1) {
    extern __shared__ float sm0[];
    float* simg = sm0;
    float* sw   = sm0 + 256 * 91;
    float* sb   = sw + 32;
    const int t  = threadIdx.x;
    const int B0 = blockIdx.x * 256;
    const int c0 = blockIdx.y * 8;

#pragma unroll 1
    for (int i = 0; i < 90; ++i) {
        int f = i * 256 + t;
        int s = f / 90, off = f - s * 90;
        simg[s * 91 + off] = img[(B0 + s) * 90 + off];
    }
    if (t < 32) sw[t] = w1[c0 * 4 + t];
    if (t < 8)  sb[t] = b1[c0 + t];
    __syncthreads();

    const int q  = t & 63;
    const int cg = t >> 6;
    float W00[2], W01[2], W10[2], W11[2], BB[2];
#pragma unroll
    for (int c2 = 0; c2 < 2; ++c2) {
        int cc = cg * 2 + c2;
        W00[c2] = sw[cc * 4 + 0]; W01[c2] = sw[cc * 4 + 1];
        W10[c2] = sw[cc * 4 + 2]; W11[c2] = sw[cc * 4 + 3];
        BB[c2]  = sb[cc];
    }

#pragma unroll 1
    for (int h = 0; h < 10; ++h) {
        float a[4][9], b[4][9];
        const bool hb = (h < 9);
#pragma unroll
        for (int s = 0; s < 4; ++s) {
            const float* rp = simg + (q * 4 + s) * 91 + h * 9;
#pragma unroll
            for (int w = 0; w < 9; ++w) {
                a[s][w] = rp[w];
                b[s][w] = hb ? rp[9 + w] : 0.f;
            }
        }
#pragma unroll
        for (int c2 = 0; c2 < 2; ++c2) {
            const int c = c0 + cg * 2 + c2;
            float* op = g_conv + ((size_t)c * 90 + h * 9) * B_TOTAL + B0 + q * 4;
            const float w00 = W00[c2], w01 = W01[c2], w10 = W10[c2], w11 = W11[c2], bv = BB[c2];
#pragma unroll
            for (int w = 0; w < 9; ++w) {
                float v[4];
#pragma unroll
                for (int s = 0; s < 4; ++s) {
                    float t0 = fmaf(a[s][w], w00, bv);
                    if (w < 8) t0 = fmaf(a[s][w + 1], w01, t0);
                    t0 = fmaf(b[s][w], w10, t0);
                    if (w < 8) t0 = fmaf(b[s][w + 1], w11, t0);
                    v[s] = lrelu(t0);
                }
                ((float4*)(op + (size_t)w * B_TOTAL))[0] = make_float4(v[0], v[1], v[2], v[3]);
            }
        }
    }
}

// ============================ K1: LC1 direct-global GEMM =====================
// grid (50, 16), block 256. Thread: 2 samples x 16 channels. acc = 32 regs.
#define K1_BODY(PF, KIDX) do {                                               \
    float2 cur = PF;                                                         \
    { int _o = soff[(KIDX) + 3];                                             \
      PF = make_float2(0.f, 0.f);                                            \
      if (_o >= 0) PF = *(const float2*)(gA + _o); }                         \
    u64 s0 = dup2f(cur.x), s1 = dup2f(cur.y);                                \
    const ulonglong2* wp = Wv + (size_t)(KIDX) * 4;                          \
    ulonglong2 wA = wp[0], wB = wp[1], wC = wp[2], wD = wp[3];               \
    CH8(acc[0], s0); CH8(acc[1], s1);                                        \
} while (0)

__global__ void __launch_bounds__(256, 3) k1_lc1(const float* __restrict__ lcw,
                                                 const float* __restrict__ lcb) {
    __shared__ __align__(16) float Wsm[9216];   // [576][16]
    __shared__ int soff[592];
    __shared__ float red[32];
    const int t   = threadIdx.x;
    const int loc = blockIdx.x;
    const int B0  = blockIdx.y * 512;
    const int h   = loc / 5, w = loc - h * 5;

#pragma unroll
    for (int rr = 0; rr < 4; ++rr) {
        int rid = rr * 256 + t;
        int o = rid >> 6, c = rid & 63;
        const float* src = lcw + ((size_t)(o * 64 + c) * 50 + loc) * 9;
#pragma unroll
        for (int m = 0; m < 9; ++m) Wsm[(c * 9 + m) * 16 + o] = src[m];
    }
    for (int k = t; k < 592; k += 256) {
        int v = -1;
        if (k < 576) {
            int c = k / 9, m = k - 9 * c, i3 = m / 3, j3 = m - 3 * i3;
            int r = h + i3, cc = 2 * w + j3;
            if (r >= 1 && r <= 10 && cc >= 1 && cc <= 9)
                v = ((c * 10 + r - 1) * 9 + cc - 1) * B_TOTAL;
        }
        soff[k] = v;
    }
    if (t < 32) red[t] = 0.f;
    __syncthreads();

    const float* gA = g_conv + B0 + t * 2;
    const ulonglong2* Wv = (const ulonglong2*)Wsm;
    u64 acc[2][8] = {};

    float2 pf0, pf1, pf2;
    { int o = soff[0]; pf0 = make_float2(0.f, 0.f); if (o >= 0) pf0 = *(const float2*)(gA + o); }
    { int o = soff[1]; pf1 = make_float2(0.f, 0.f); if (o >= 0) pf1 = *(const float2*)(gA + o); }
    { int o = soff[2]; pf2 = make_float2(0.f, 0.f); if (o >= 0) pf2 = *(const float2*)(gA + o); }

#pragma unroll 3
    for (int k = 0; k < 576; k += 3) {
        K1_BODY(pf0, k);
        K1_BODY(pf1, k + 1);
        K1_BODY(pf2, k + 2);
    }

#pragma unroll
    for (int j = 0; j < 8; ++j) {
        const int o0 = 2 * j, o1 = 2 * j + 1;
        const float b0v = lcb[o0 * 50 + loc];
        const float b1v = lcb[o1 * 50 + loc];
        float lo0, hi0, lo1, hi1;
        UNPK(lo0, hi0, acc[0][j]);   // sample0: ch o0 (lo), o1 (hi)
        UNPK(lo1, hi1, acc[1][j]);   // sample1
        float a0 = lrelu(lo0 + b0v), a1 = lrelu(lo1 + b0v);
        float c0 = lrelu(hi0 + b1v), c1 = lrelu(hi1 + b1v);
        ((float2*)(g_y1 + ((size_t)o0 * 50 + loc) * B_TOTAL + B0))[t] = make_float2(a0, a1);
        ((float2*)(g_y1 + ((size_t)o1 * 50 + loc) * B_TOTAL + B0))[t] = make_float2(c0, c1);
        float s0 = wsum(a0 + a1), q0 = wsum(a0 * a0 + a1 * a1);
        float s1 = wsum(c0 + c1), q1 = wsum(c0 * c0 + c1 * c1);
        if ((t & 31) == 0) {
            atomicAdd(&red[o0 * 2 + 0], s0); atomicAdd(&red[o0 * 2 + 1], q0);
            atomicAdd(&red[o1 * 2 + 0], s1); atomicAdd(&red[o1 * 2 + 1], q1);
        }
    }
    __syncthreads();
    if (t < 32) g_part1[(blockIdx.y * 50 + loc) * 32 + t] = red[t];
}

// ============================ K3/K5 common body ===============================
// 4 samples/thread as 2 natural f32x2 pairs; weights BN-scaled + dup'd in smem.
#define LC_BODY(FA, KIDX) do {                                               \
    ulonglong2 a01 = FA;                                                     \
    { int _o = soff[(KIDX) + 2];                                             \
      FA.x = 0ULL; FA.y = 0ULL;                                              \
      if (_o >= 0) FA = *(const ulonglong2*)(gA + _o); }                     \
    const ulonglong2* wp = (const ulonglong2*)(Wd + (size_t)(KIDX) * 8);     \
    ulonglong2 wA = wp[0], wB = wp[1], wC = wp[2], wD = wp[3];               \
    CH8(acc[0], a01.x); CH8(acc[1], a01.y);                                  \
} while (0)

// ============================ K3: BN1(folded) + pad + LC2 =====================
// grid (66, 16), block 128. Thread: 4 samples x 8 channels.
__global__ void __launch_bounds__(128, 6) k3_lc2(const float* __restrict__ lcw,
                                                 const float* __restrict__ lcb) {
    __shared__ __align__(16) u64 Wd[512];       // [64][8] dup'd, scaled by bnA
    __shared__ float biasc[8];
    __shared__ int soff[68];
    __shared__ float red[16];
    const int t   = threadIdx.x;
    const int loc = blockIdx.x;
    const int B0  = blockIdx.y * 512;
    const int h2  = loc / 6, w2 = loc - h2 * 6;

#pragma unroll
    for (int rr = 0; rr < 4; ++rr) {
        int idx = rr * 128 + t;                 // k*8 + o
        int o = idx & 7, k = idx >> 3;
        int c = k >> 2;
        float wv = lcw[(size_t)((o * 16 + c) * 66 + loc) * 4 + (k & 3)];
        Wd[idx] = dup2f(wv * g_bnA1[c]);
    }
    for (int k = t; k < 68; k += 128) {
        int v = -1;
        if (k < 64) {
            int c = k >> 2, m = k & 3;
            int hp = h2 + (m >> 1), wp = w2 + (m & 1);
            if (hp >= 1 && hp <= 10 && wp >= 1 && wp <= 5)
                v = (c * 50 + (hp - 1) * 5 + (wp - 1)) * B_TOTAL;
        }
        soff[k] = v;
    }
    if (t < 16) red[t] = 0.f;
    if (t < 8) {
        float s = 0.f;
#pragma unroll 1
        for (int k = 0; k < 64; ++k) {
            int c = k >> 2, m = k & 3;
            int hp = h2 + (m >> 1), wp = w2 + (m & 1);
            if (hp >= 1 && hp <= 10 && wp >= 1 && wp <= 5)
                s += lcw[(size_t)((t * 16 + c) * 66 + loc) * 4 + m] * g_bnB1[c];
        }
        biasc[t] = s;
    }
    __syncthreads();

    const float* gA = g_y1 + B0 + t * 4;
    u64 acc[2][8] = {};
    ulonglong2 f0, f1;
    { int o = soff[0]; f0.x = f0.y = 0ULL; if (o >= 0) f0 = *(const ulonglong2*)(gA + o); }
    { int o = soff[1]; f1.x = f1.y = 0ULL; if (o >= 0) f1 = *(const ulonglong2*)(gA + o); }

#pragma unroll 4
    for (int k = 0; k < 64; k += 2) {
        LC_BODY(f0, k);
        LC_BODY(f1, k + 1);
    }

#pragma unroll
    for (int o = 0; o < 8; ++o) {
        const float bv = lcb[o * 66 + loc] + biasc[o];
        float v0, v1, v2, v3;
        UNPK(v0, v1, acc[0][o]);
        UNPK(v2, v3, acc[1][o]);
        v0 = lrelu(v0 + bv); v1 = lrelu(v1 + bv);
        v2 = lrelu(v2 + bv); v3 = lrelu(v3 + bv);
        ((float4*)(g_y2 + ((size_t)o * 66 + loc) * B_TOTAL + B0))[t] =
            make_float4(v0, v1, v2, v3);
        float s = wsum(v0 + v1 + v2 + v3);
        float q = wsum(v0 * v0 + v1 * v1 + v2 * v2 + v3 * v3);
        if ((t & 31) == 0) {
            atomicAdd(&red[o * 2 + 0], s);
            atomicAdd(&red[o * 2 + 1], q);
        }
    }
    __syncthreads();
    if (t < 16) g_part2[(blockIdx.y * 66 + loc) * 16 + t] = red[t];
}

// ============================ K5: BN2(folded) + pad + LC3 =====================
// grid (48, 16), block 128. Thread: 4 samples x 8 channels.
__global__ void __launch_bounds__(128, 6) k5_lc3(const float* __restrict__ lcw,
                                                 const float* __restrict__ lcb) {
    __shared__ __align__(16) u64 Wd[256];       // [32][8] dup'd, scaled by bnA
    __shared__ float biasc[8];
    __shared__ int soff[36];
    __shared__ float red[16];
    const int t   = threadIdx.x;
    const int loc = blockIdx.x;
    const int B0  = blockIdx.y * 512;
    const int h3  = loc >> 2, w3 = loc & 3;

#pragma unroll
    for (int rr = 0; rr < 2; ++rr) {
        int idx = rr * 128 + t;
        int o = idx & 7, k = idx >> 3;
        int c = k >> 2;
        float wv = lcw[(size_t)((o * 8 + c) * 48 + loc) * 4 + (k & 3)];
        Wd[idx] = dup2f(wv * g_bnA2[c]);
    }
    for (int k = t; k < 36; k += 128) {
        int v = -1;
        if (k < 32) {
            int c = k >> 2, m = k & 3;
            int hp = h3 + (m >> 1), wp = 2 * w3 + (m & 1);
            if (hp >= 1 && hp <= 11 && wp >= 1 && wp <= 6)
                v = (c * 66 + (hp - 1) * 6 + (wp - 1)) * B_TOTAL;
        }
        soff[k] = v;
    }
    if (t < 16) red[t] = 0.f;
    if (t < 8) {
        float s = 0.f;
#pragma unroll 1
        for (int k = 0; k < 32; ++k) {
            int c = k >> 2, m = k & 3;
            int hp = h3 + (m >> 1), wp = 2 * w3 + (m & 1);
            if (hp >= 1 && hp <= 11 && wp >= 1 && wp <= 6)
                s += lcw[(size_t)((t * 8 + c) * 48 + loc) * 4 + m] * g_bnB2[c];
        }
        biasc[t] = s;
    }
    __syncthreads();

    const float* gA = g_y2 + B0 + t * 4;
    u64 acc[2][8] = {};
    ulonglong2 f0, f1;
    { int o = soff[0]; f0.x = f0.y = 0ULL; if (o >= 0) f0 = *(const ulonglong2*)(gA + o); }
    { int o = soff[1]; f1.x = f1.y = 0ULL; if (o >= 0) f1 = *(const ulonglong2*)(gA + o); }

#pragma unroll 4
    for (int k = 0; k < 32; k += 2) {
        LC_BODY(f0, k);
        LC_BODY(f1, k + 1);
    }

#pragma unroll
    for (int o = 0; o < 8; ++o) {
        const float bv = lcb[o * 48 + loc] + biasc[o];
        float v0, v1, v2, v3;
        UNPK(v0, v1, acc[0][o]);
        UNPK(v2, v3, acc[1][o]);
        v0 = lrelu(v0 + bv); v1 = lrelu(v1 + bv);
        v2 = lrelu(v2 + bv); v3 = lrelu(v3 + bv);
        ((float4*)(g_y3 + ((size_t)o * 48 + loc) * B_TOTAL + B0))[t] =
            make_float4(v0, v1, v2, v3);
        float s = wsum(v0 + v1 + v2 + v3);
        float q = wsum(v0 * v0 + v1 * v1 + v2 * v2 + v3 * v3);
        if ((t & 31) == 0) {
            atomicAdd(&red[o * 2 + 0], s);
            atomicAdd(&red[o * 2 + 1], q);
        }
    }
    __syncthreads();
    if (t < 16) g_part3[(blockIdx.y * 48 + loc) * 16 + t] = red[t];
}

// ============================ stat reducer ====================================
__global__ void kred(int stage, int nb, int nch, float invN,
                     const float* __restrict__ gamma, const float* __restrict__ beta) {
    __shared__ float sm[1024];
    const float* part = (stage == 0) ? g_part1 : (stage == 1) ? g_part2 : g_part3;
    float* bnA = (stage == 0) ? g_bnA1 : (stage == 1) ? g_bnA2 : g_bnA3;
    float* bnB = (stage == 0) ? g_bnB1 : (stage == 1) ? g_bnB2 : g_bnB3;
    const int t = threadIdx.x;
    const int slots = 2 * nch;
    const int grp = t % slots;
    const int lane = t / slots;
    const int per = blockDim.x / slots;
    float s = 0.f;
    for (int i = lane; i < nb; i += per) s += part[i * slots + grp];
    sm[t] = s;
    __syncthreads();
    for (int step = per >> 1; step > 0; step >>= 1) {
        if (lane < step) sm[t] += sm[t + step * slots];
        __syncthreads();
    }
    if (t < nch) {
        float sum = sm[t * 2 + 0], sq = sm[t * 2 + 1];
        float mean = sum * invN;
        float var = sq * invN - mean * mean;
        float rs = rsqrtf(var + BN_EPS);
        float g = gamma[t];
        bnA[t] = g * rs;
        bnB[t] = beta[t] - mean * g * rs;
    }
}

// ============================ K7: BN3 + transpose to output ===================
__global__ void k7_out(float* __restrict__ out) {
    __shared__ float tile[32][65];
    __shared__ float a3[8], b3[8];
    const int t  = threadIdx.x;
    const int f0 = blockIdx.x * 32;
    const int b0 = blockIdx.y * 64;
    if (t < 8) { a3[t] = g_bnA3[t]; b3[t] = g_bnB3[t]; }
    __syncthreads();
#pragma unroll
    for (int r = 0; r < 8; ++r) {
        int f = r * 4 + (t >> 6);
        int b = t & 63;
        float v = g_y3[(size_t)(f0 + f) * B_TOTAL + b0 + b];
        int c = (f0 + f) / 48;
        tile[f][b] = fmaf(a3[c], v, b3[c]);
    }
    __syncthreads();
#pragma unroll
    for (int r = 0; r < 8; ++r) {
        int f = t & 31;
        int b = r * 8 + (t >> 5);
        out[(size_t)(b0 + b) * 384 + f0 + f] = tile[f][b];
    }
}

// ============================ launch ==========================================
extern "C" void kernel_launch(void* const* d_in, const int* in_sizes, int n_in,
                              void* d_out, int out_size) {
    const float* image = (const float*)d_in[0];
    const float* c1w   = (const float*)d_in[1];
    const float* c1b   = (const float*)d_in[2];
    const float* lc1w  = (const float*)d_in[3];
    const float* lc1b  = (const float*)d_in[4];
    const float* lc2w  = (const float*)d_in[5];
    const float* lc2b  = (const float*)d_in[6];
    const float* lc3w  = (const float*)d_in[7];
    const float* lc3b  = (const float*)d_in[8];
    const float* g1    = (const float*)d_in[9];
    const float* be1   = (const float*)d_in[10];
    const float* g2    = (const float*)d_in[11];
    const float* be2   = (const float*)d_in[12];
    const float* g3    = (const float*)d_in[13];
    const float* be3   = (const float*)d_in[14];
    float* out = (float*)d_out;

    cudaFuncSetAttribute(k0_conv1, cudaFuncAttributeMaxDynamicSharedMemorySize, SMEM0);

    k0_conv1<<<dim3(32, 8),   256, SMEM0>>>(image, c1w, c1b);
    k1_lc1  <<<dim3(50, 16),  256>>>(lc1w, lc1b);
    kred    <<<1, 1024>>>(0, 800,  16, 1.0f / (8192.0f * 50.0f), g1, be1);
    k3_lc2  <<<dim3(66, 16),  128>>>(lc2w, lc2b);
    kred    <<<1, 1024>>>(1, 1056, 8,  1.0f / (8192.0f * 66.0f), g2, be2);
    k5_lc3  <<<dim3(48, 16),  128>>>(lc3w, lc3b);
    kred    <<<1, 1024>>>(2, 768,  8,  1.0f / (8192.0f * 48.0f), g3, be3);
    k7_out  <<<dim3(12, 128), 256>>>(out);
}

// round 6
// speedup vs baseline: 1.0015x; 1.0015x over previous
#include <cuda_runtime.h>
#include <cstdint>

#define B_TOTAL   8192
#define LEAK      0.01f
#define BN_EPS    1e-5f

// -------------------- global scratch --------------------
__device__ float g_conv[64 * 90 * B_TOTAL];   // conv1 out [64][10][9][B]
__device__ float g_y1[16 * 50 * B_TOTAL];
__device__ float g_y2[8 * 66 * B_TOTAL];
__device__ float g_y3[8 * 48 * B_TOTAL];
__device__ float g_part1[400 * 32];
__device__ float g_part2[528 * 16];
__device__ float g_part3[384 * 16];
__device__ float g_bnA1[16], g_bnB1[16];
__device__ float g_bnA2[8],  g_bnB2[8];
__device__ float g_bnA3[8],  g_bnB3[8];

typedef unsigned long long u64;

__device__ __forceinline__ float lrelu(float v) { return v < 0.f ? LEAK * v : v; }
__device__ __forceinline__ float wsum(float v) {
#pragma unroll
    for (int s = 16; s; s >>= 1) v += __shfl_xor_sync(0xffffffffu, v, s);
    return v;
}
__device__ __forceinline__ u64 dup2f(float v) {
    u64 r; asm("mov.b64 %0, {%1, %1};" : "=l"(r) : "f"(v)); return r;
}
#define FMA2(d, a, b)   asm("fma.rn.f32x2 %0, %1, %2, %0;" : "+l"(d) : "l"(a), "l"(b))
#define UNPK(lo, hi, v) asm("mov.b64 {%0, %1}, %2;" : "=f"(lo), "=f"(hi) : "l"(v))

#define CH8(ar, s)                                              \
    FMA2(ar[0], s, wA.x); FMA2(ar[1], s, wA.y);                 \
    FMA2(ar[2], s, wB.x); FMA2(ar[3], s, wB.y);                 \
    FMA2(ar[4], s, wC.x); FMA2(ar[5], s, wC.y);                 \
    FMA2(ar[6], s, wD.x); FMA2(ar[7], s, wD.y);

// ============================ K0: conv1 + lrelu ===============================
#define SMEM0 ((256 * 91 + 32 + 8) * 4)
__global__ void k0_conv1(const float* __restrict__ img,
                         const float* __restrict__ w1,
                         const float* __restrict__ b1) {
    extern __shared__ float sm0[];
    float* simg = sm0;
    float* sw   = sm0 + 256 * 91;
    float* sb   = sw + 32;
    const int t  = threadIdx.x;
    const int B0 = blockIdx.x * 256;
    const int c0 = blockIdx.y * 8;

#pragma unroll 1
    for (int i = 0; i < 90; ++i) {
        int f = i * 256 + t;
        int s = f / 90, off = f - s * 90;
        simg[s * 91 + off] = img[(B0 + s) * 90 + off];
    }
    if (t < 32) sw[t] = w1[c0 * 4 + t];
    if (t < 8)  sb[t] = b1[c0 + t];
    __syncthreads();

    const int q  = t & 63;
    const int cg = t >> 6;
    float W00[2], W01[2], W10[2], W11[2], BB[2];
#pragma unroll
    for (int c2 = 0; c2 < 2; ++c2) {
        int cc = cg * 2 + c2;
        W00[c2] = sw[cc * 4 + 0]; W01[c2] = sw[cc * 4 + 1];
        W10[c2] = sw[cc * 4 + 2]; W11[c2] = sw[cc * 4 + 3];
        BB[c2]  = sb[cc];
    }

#pragma unroll 1
    for (int h = 0; h < 10; ++h) {
        float a[4][9], b[4][9];
        const bool hb = (h < 9);
#pragma unroll
        for (int s = 0; s < 4; ++s) {
            const float* rp = simg + (q * 4 + s) * 91 + h * 9;
#pragma unroll
            for (int w = 0; w < 9; ++w) {
                a[s][w] = rp[w];
                b[s][w] = hb ? rp[9 + w] : 0.f;
            }
        }
#pragma unroll
        for (int c2 = 0; c2 < 2; ++c2) {
            const int c = c0 + cg * 2 + c2;
            float* op = g_conv + ((size_t)c * 90 + h * 9) * B_TOTAL + B0 + q * 4;
            const float w00 = W00[c2], w01 = W01[c2], w10 = W10[c2], w11 = W11[c2], bv = BB[c2];
#pragma unroll
            for (int w = 0; w < 9; ++w) {
                float v[4];
#pragma unroll
                for (int s = 0; s < 4; ++s) {
                    float t0 = fmaf(a[s][w], w00, bv);
                    if (w < 8) t0 = fmaf(a[s][w + 1], w01, t0);
                    t0 = fmaf(b[s][w], w10, t0);
                    if (w < 8) t0 = fmaf(b[s][w + 1], w11, t0);
                    v[s] = lrelu(t0);
                }
                ((float4*)(op + (size_t)w * B_TOTAL))[0] = make_float4(v[0], v[1], v[2], v[3]);
            }
        }
    }
}

// ============================ K1: LC1 compacted direct GEMM ===================
// grid (50, 8), block 256. Thread: 4 samples x 16 ch. Only VALID k iterated.
// Compact index kk = m'*64 + c;  nv = nIJ*64 in {256,384,576} (all % 4 == 0).
#define K1_BODY(PF, KIDX) do {                                               \
    float4 cur = PF;                                                         \
    PF = *(const float4*)(gA + soff[(KIDX) + 4]);                            \
    u64 s0 = dup2f(cur.x), s1 = dup2f(cur.y);                                \
    u64 s2 = dup2f(cur.z), s3 = dup2f(cur.w);                                \
    const ulonglong2* wp = Wv + (size_t)(KIDX) * 4;                          \
    ulonglong2 wA = wp[0], wB = wp[1], wC = wp[2], wD = wp[3];               \
    CH8(acc[0], s0); CH8(acc[1], s1); CH8(acc[2], s2); CH8(acc[3], s3);      \
} while (0)

__global__ void __launch_bounds__(256, 2) k1_lc1(const float* __restrict__ lcw,
                                                 const float* __restrict__ lcb) {
    __shared__ __align__(16) float Wsm[9216];   // [nv][16] compact
    __shared__ int soff[580];                   // nv + 4 pad
    __shared__ float red[32];
    __shared__ int smi[9], smj[9];
    const int t   = threadIdx.x;
    const int loc = blockIdx.x;
    const int B0  = blockIdx.y * 1024;
    const int h   = loc / 5, w = loc - h * 5;

    const int i3lo = (h == 0) ? 1 : 0, i3hi = (h == 9) ? 1 : 2;
    const int j3lo = (w == 0) ? 1 : 0, j3hi = (w == 4) ? 1 : 2;
    const int nI = i3hi - i3lo + 1, nJ = j3hi - j3lo + 1;
    const int nIJ = nI * nJ;
    const int nv = nIJ * 64;

    if (t < 9) { smi[t] = i3lo + t / nJ; smj[t] = j3lo + t - (t / nJ) * nJ; }
    if (t < 32) red[t] = 0.f;
    __syncthreads();

    // compact weight fill: 1024 (o,c) pairs, each writes nIJ compact rows
#pragma unroll
    for (int rr = 0; rr < 4; ++rr) {
        int rid = rr * 256 + t;
        int o = rid >> 6, c = rid & 63;
        const float* src = lcw + ((size_t)(o * 64 + c) * 50 + loc) * 9;
#pragma unroll 1
        for (int m = 0; m < nIJ; ++m)
            Wsm[((m << 6) + c) * 16 + o] = src[smi[m] * 3 + smj[m]];
    }
    // compact offsets (always valid)
    for (int kk = t; kk < nv + 4; kk += 256) {
        int v = 0;
        if (kk < nv) {
            int c = kk & 63, m = kk >> 6;
            v = ((c * 10 + h + smi[m] - 1) * 9 + (2 * w + smj[m] - 1)) * B_TOTAL;
        }
        soff[kk] = v;
    }
    __syncthreads();

    const float* gA = g_conv + B0 + t * 4;
    const ulonglong2* Wv = (const ulonglong2*)Wsm;
    u64 acc[4][8] = {};

    float4 pf0 = *(const float4*)(gA + soff[0]);
    float4 pf1 = *(const float4*)(gA + soff[1]);
    float4 pf2 = *(const float4*)(gA + soff[2]);
    float4 pf3 = *(const float4*)(gA + soff[3]);

#pragma unroll 1
    for (int k = 0; k < nv; k += 4) {
        K1_BODY(pf0, k);
        K1_BODY(pf1, k + 1);
        K1_BODY(pf2, k + 2);
        K1_BODY(pf3, k + 3);
    }

#pragma unroll
    for (int j = 0; j < 8; ++j) {
        const int o0 = 2 * j, o1 = 2 * j + 1;
        const float b0v = lcb[o0 * 50 + loc];
        const float b1v = lcb[o1 * 50 + loc];
        float lo[4], hi[4];
#pragma unroll
        for (int s = 0; s < 4; ++s) UNPK(lo[s], hi[s], acc[s][j]);
        float a0 = lrelu(lo[0] + b0v), a1 = lrelu(lo[1] + b0v);
        float a2 = lrelu(lo[2] + b0v), a3 = lrelu(lo[3] + b0v);
        float c0 = lrelu(hi[0] + b1v), c1 = lrelu(hi[1] + b1v);
        float c2 = lrelu(hi[2] + b1v), c3 = lrelu(hi[3] + b1v);
        ((float4*)(g_y1 + ((size_t)o0 * 50 + loc) * B_TOTAL + B0))[t] = make_float4(a0, a1, a2, a3);
        ((float4*)(g_y1 + ((size_t)o1 * 50 + loc) * B_TOTAL + B0))[t] = make_float4(c0, c1, c2, c3);
        float s0 = wsum(a0 + a1 + a2 + a3), q0 = wsum(a0*a0 + a1*a1 + a2*a2 + a3*a3);
        float s1 = wsum(c0 + c1 + c2 + c3), q1 = wsum(c0*c0 + c1*c1 + c2*c2 + c3*c3);
        if ((t & 31) == 0) {
            atomicAdd(&red[o0 * 2 + 0], s0); atomicAdd(&red[o0 * 2 + 1], q0);
            atomicAdd(&red[o1 * 2 + 0], s1); atomicAdd(&red[o1 * 2 + 1], q1);
        }
    }
    __syncthreads();
    if (t < 32) g_part1[(blockIdx.y * 50 + loc) * 32 + t] = red[t];
}

// ============================ K3/K5 common body ===============================
// 8 samples/thread as 4 natural f32x2 pairs; weights BN-scaled + dup'd, compact.
#define LC_BODY(FA, FB, KIDX) do {                                           \
    ulonglong2 a01 = FA, a23 = FB;                                           \
    { const ulonglong2* _p = (const ulonglong2*)(gA + soff[(KIDX) + 2]);     \
      FA = _p[0]; FB = _p[1]; }                                              \
    const ulonglong2* wp = (const ulonglong2*)(Wd + (size_t)(KIDX) * 8);     \
    ulonglong2 wA = wp[0], wB = wp[1], wC = wp[2], wD = wp[3];               \
    CH8(acc[0], a01.x); CH8(acc[1], a01.y);                                  \
    CH8(acc[2], a23.x); CH8(acc[3], a23.y);                                  \
} while (0)

// ============================ K3: BN1(folded) + LC2, compacted ================
// grid (66, 8), block 128. Thread: 8 samples x 8 ch. kk = m'*16 + c, nv in {16,32,64}.
__global__ void __launch_bounds__(128, 4) k3_lc2(const float* __restrict__ lcw,
                                                 const float* __restrict__ lcb) {
    __shared__ __align__(16) u64 Wd[512];       // [nv][8] dup'd, bnA-folded
    __shared__ float biasc[8];
    __shared__ int soff[66];                    // nv + 2 pad
    __shared__ float red[16];
    __shared__ int smi[4], smj[4];
    const int t   = threadIdx.x;
    const int loc = blockIdx.x;
    const int B0  = blockIdx.y * 1024;
    const int h2  = loc / 6, w2 = loc - h2 * 6;

    const int ilo = (h2 == 0) ? 1 : 0, ihi = (h2 == 10) ? 0 : 1;
    const int jlo = (w2 == 0) ? 1 : 0, jhi = (w2 == 5) ? 0 : 1;
    const int nI = ihi - ilo + 1, nJ = jhi - jlo + 1;
    const int nIJ = nI * nJ;
    const int nv = nIJ * 16;

    if (t < 4) { smi[t] = ilo + t / nJ; smj[t] = jlo + t - (t / nJ) * nJ; }
    if (t < 16) red[t] = 0.f;
    __syncthreads();

    // compact weights (<= 512 entries)
    for (int f = t; f < nv * 8; f += 128) {
        int kk = f >> 3, o = f & 7;
        int c = kk & 15, m = kk >> 4;
        float wv = lcw[(size_t)((o * 16 + c) * 66 + loc) * 4 + smi[m] * 2 + smj[m]];
        Wd[f] = dup2f(wv * g_bnA1[c]);
    }
    for (int kk = t; kk < nv + 2; kk += 128) {
        int v = 0;
        if (kk < nv) {
            int c = kk & 15, m = kk >> 4;
            v = (c * 50 + (h2 + smi[m] - 1) * 5 + (w2 + smj[m] - 1)) * B_TOTAL;
        }
        soff[kk] = v;
    }
    if (t < 8) {
        float s = 0.f;
#pragma unroll 1
        for (int kk = 0; kk < nv; ++kk) {
            int c = kk & 15, m = kk >> 4;
            s += lcw[(size_t)((t * 16 + c) * 66 + loc) * 4 + smi[m] * 2 + smj[m]] * g_bnB1[c];
        }
        biasc[t] = s;
    }
    __syncthreads();

    const float* gA = g_y1 + B0 + t * 8;
    u64 acc[4][8] = {};
    ulonglong2 f0a, f0b, f1a, f1b;
    { const ulonglong2* p = (const ulonglong2*)(gA + soff[0]); f0a = p[0]; f0b = p[1]; }
    { const ulonglong2* p = (const ulonglong2*)(gA + soff[1]); f1a = p[0]; f1b = p[1]; }

#pragma unroll 1
    for (int k = 0; k < nv; k += 2) {
        LC_BODY(f0a, f0b, k);
        LC_BODY(f1a, f1b, k + 1);
    }

#pragma unroll
    for (int o = 0; o < 8; ++o) {
        const float bv = lcb[o * 66 + loc] + biasc[o];
        float v[8];
#pragma unroll
        for (int p = 0; p < 4; ++p) UNPK(v[2 * p], v[2 * p + 1], acc[p][o]);
#pragma unroll
        for (int p = 0; p < 8; ++p) v[p] = lrelu(v[p] + bv);
        float* dst = g_y2 + ((size_t)o * 66 + loc) * B_TOTAL + B0 + t * 8;
        ((float4*)dst)[0] = make_float4(v[0], v[1], v[2], v[3]);
        ((float4*)dst)[1] = make_float4(v[4], v[5], v[6], v[7]);
        float s = wsum(v[0]+v[1]+v[2]+v[3]+v[4]+v[5]+v[6]+v[7]);
        float q = wsum(v[0]*v[0]+v[1]*v[1]+v[2]*v[2]+v[3]*v[3]
                     + v[4]*v[4]+v[5]*v[5]+v[6]*v[6]+v[7]*v[7]);
        if ((t & 31) == 0) {
            atomicAdd(&red[o * 2 + 0], s);
            atomicAdd(&red[o * 2 + 1], q);
        }
    }
    __syncthreads();
    if (t < 16) g_part2[(blockIdx.y * 66 + loc) * 16 + t] = red[t];
}

// ============================ K5: BN2(folded) + LC3, compacted ================
// grid (48, 8), block 128. kk = m'*8 + c, nv in {8,16,32}.
__global__ void __launch_bounds__(128, 4) k5_lc3(const float* __restrict__ lcw,
                                                 const float* __restrict__ lcb) {
    __shared__ __align__(16) u64 Wd[256];
    __shared__ float biasc[8];
    __shared__ int soff[34];
    __shared__ float red[16];
    __shared__ int smi[4], smj[4];
    const int t   = threadIdx.x;
    const int loc = blockIdx.x;
    const int B0  = blockIdx.y * 1024;
    const int h3  = loc >> 2, w3 = loc & 3;

    const int ilo = (h3 == 0) ? 1 : 0, ihi = (h3 == 11) ? 0 : 1;
    const int jlo = (w3 == 0) ? 1 : 0, jhi = (w3 == 3) ? 0 : 1;
    const int nI = ihi - ilo + 1, nJ = jhi - jlo + 1;
    const int nIJ = nI * nJ;
    const int nv = nIJ * 8;

    if (t < 4) { smi[t] = ilo + t / nJ; smj[t] = jlo + t - (t / nJ) * nJ; }
    if (t < 16) red[t] = 0.f;
    __syncthreads();

    for (int f = t; f < nv * 8; f += 128) {
        int kk = f >> 3, o = f & 7;
        int c = kk & 7, m = kk >> 3;
        float wv = lcw[(size_t)((o * 8 + c) * 48 + loc) * 4 + smi[m] * 2 + smj[m]];
        Wd[f] = dup2f(wv * g_bnA2[c]);
    }
    for (int kk = t; kk < nv + 2; kk += 128) {
        int v = 0;
        if (kk < nv) {
            int c = kk & 7, m = kk >> 3;
            v = (c * 66 + (h3 + smi[m] - 1) * 6 + (2 * w3 + smj[m] - 1)) * B_TOTAL;
        }
        soff[kk] = v;
    }
    if (t < 8) {
        float s = 0.f;
#pragma unroll 1
        for (int kk = 0; kk < nv; ++kk) {
            int c = kk & 7, m = kk >> 3;
            s += lcw[(size_t)((t * 8 + c) * 48 + loc) * 4 + smi[m] * 2 + smj[m]] * g_bnB2[c];
        }
        biasc[t] = s;
    }
    __syncthreads();

    const float* gA = g_y2 + B0 + t * 8;
    u64 acc[4][8] = {};
    ulonglong2 f0a, f0b, f1a, f1b;
    { const ulonglong2* p = (const ulonglong2*)(gA + soff[0]); f0a = p[0]; f0b = p[1]; }
    { const ulonglong2* p = (const ulonglong2*)(gA + soff[1]); f1a = p[0]; f1b = p[1]; }

#pragma unroll 1
    for (int k = 0; k < nv; k += 2) {
        LC_BODY(f0a, f0b, k);
        LC_BODY(f1a, f1b, k + 1);
    }

#pragma unroll
    for (int o = 0; o < 8; ++o) {
        const float bv = lcb[o * 48 + loc] + biasc[o];
        float v[8];
#pragma unroll
        for (int p = 0; p < 4; ++p) UNPK(v[2 * p], v[2 * p + 1], acc[p][o]);
#pragma unroll
        for (int p = 0; p < 8; ++p) v[p] = lrelu(v[p] + bv);
        float* dst = g_y3 + ((size_t)o * 48 + loc) * B_TOTAL + B0 + t * 8;
        ((float4*)dst)[0] = make_float4(v[0], v[1], v[2], v[3]);
        ((float4*)dst)[1] = make_float4(v[4], v[5], v[6], v[7]);
        float s = wsum(v[0]+v[1]+v[2]+v[3]+v[4]+v[5]+v[6]+v[7]);
        float q = wsum(v[0]*v[0]+v[1]*v[1]+v[2]*v[2]+v[3]*v[3]
                     + v[4]*v[4]+v[5]*v[5]+v[6]*v[6]+v[7]*v[7]);
        if ((t & 31) == 0) {
            atomicAdd(&red[o * 2 + 0], s);
            atomicAdd(&red[o * 2 + 1], q);
        }
    }
    __syncthreads();
    if (t < 16) g_part3[(blockIdx.y * 48 + loc) * 16 + t] = red[t];
}

// ============================ stat reducer ====================================
__global__ void kred(int stage, int nb, int nch, float invN,
                     const float* __restrict__ gamma, const float* __restrict__ beta) {
    __shared__ float sm[1024];
    const float* part = (stage == 0) ? g_part1 : (stage == 1) ? g_part2 : g_part3;
    float* bnA = (stage == 0) ? g_bnA1 : (stage == 1) ? g_bnA2 : g_bnA3;
    float* bnB = (stage == 0) ? g_bnB1 : (stage == 1) ? g_bnB2 : g_bnB3;
    const int t = threadIdx.x;
    const int slots = 2 * nch;
    const int grp = t % slots;
    const int lane = t / slots;
    const int per = blockDim.x / slots;
    float s = 0.f;
    for (int i = lane; i < nb; i += per) s += part[i * slots + grp];
    sm[t] = s;
    __syncthreads();
    for (int step = per >> 1; step > 0; step >>= 1) {
        if (lane < step) sm[t] += sm[t + step * slots];
        __syncthreads();
    }
    if (t < nch) {
        float sum = sm[t * 2 + 0], sq = sm[t * 2 + 1];
        float mean = sum * invN;
        float var = sq * invN - mean * mean;
        float rs = rsqrtf(var + BN_EPS);
        float g = gamma[t];
        bnA[t] = g * rs;
        bnB[t] = beta[t] - mean * g * rs;
    }
}

// ============================ K7: BN3 + transpose to output ===================
__global__ void k7_out(float* __restrict__ out) {
    __shared__ float tile[32][65];
    __shared__ float a3[8], b3[8];
    const int t  = threadIdx.x;
    const int f0 = blockIdx.x * 32;
    const int b0 = blockIdx.y * 64;
    if (t < 8) { a3[t] = g_bnA3[t]; b3[t] = g_bnB3[t]; }
    __syncthreads();
#pragma unroll
    for (int r = 0; r < 8; ++r) {
        int f = r * 4 + (t >> 6);
        int b = t & 63;
        float v = g_y3[(size_t)(f0 + f) * B_TOTAL + b0 + b];
        int c = (f0 + f) / 48;
        tile[f][b] = fmaf(a3[c], v, b3[c]);
    }
    __syncthreads();
#pragma unroll
    for (int r = 0; r < 8; ++r) {
        int f = t & 31;
        int b = r * 8 + (t >> 5);
        out[(size_t)(b0 + b) * 384 + f0 + f] = tile[f][b];
    }
}

// ============================ launch ==========================================
extern "C" void kernel_launch(void* const* d_in, const int* in_sizes, int n_in,
                              void* d_out, int out_size) {
    const float* image = (const float*)d_in[0];
    const float* c1w   = (const float*)d_in[1];
    const float* c1b   = (const float*)d_in[2];
    const float* lc1w  = (const float*)d_in[3];
    const float* lc1b  = (const float*)d_in[4];
    const float* lc2w  = (const float*)d_in[5];
    const float* lc2b  = (const float*)d_in[6];
    const float* lc3w  = (const float*)d_in[7];
    const float* lc3b  = (const float*)d_in[8];
    const float* g1    = (const float*)d_in[9];
    const float* be1   = (const float*)d_in[10];
    const float* g2    = (const float*)d_in[11];
    const float* be2   = (const float*)d_in[12];
    const float* g3    = (const float*)d_in[13];
    const float* be3   = (const float*)d_in[14];
    float* out = (float*)d_out;

    cudaFuncSetAttribute(k0_conv1, cudaFuncAttributeMaxDynamicSharedMemorySize, SMEM0);

    k0_conv1<<<dim3(32, 8),   256, SMEM0>>>(image, c1w, c1b);
    k1_lc1  <<<dim3(50, 8),   256>>>(lc1w, lc1b);
    kred    <<<1, 1024>>>(0, 400, 16, 1.0f / (8192.0f * 50.0f), g1, be1);
    k3_lc2  <<<dim3(66, 8),   128>>>(lc2w, lc2b);
    kred    <<<1, 1024>>>(1, 528, 8,  1.0f / (8192.0f * 66.0f), g2, be2);
    k5_lc3  <<<dim3(48, 8),   128>>>(lc3w, lc3b);
    kred    <<<1, 1024>>>(2, 384, 8,  1.0f / (8192.0f * 48.0f), g3, be3);
    k7_out  <<<dim3(12, 128), 256>>>(out);
}